// round 2
// baseline (speedup 1.0000x reference)
#include <cuda_runtime.h>
#include <math.h>

#define DD 128
#define SS 4096
#define BB 4

// Scratch for Q/K/V projections (no cudaMalloc allowed).
__device__ float g_Q[BB * SS * DD];
__device__ float g_K[BB * SS * DD];
__device__ float g_V[BB * SS * DD];

// ---------------- QKV projection: out = x @ W for 3 weights ----------------
#define GROWS 128
#define GTH 256

struct GemmSmem {
    float x[GROWS][DD + 4];   // stride 132 floats (16B-aligned rows)
    float w[DD][DD + 4];
};

__global__ __launch_bounds__(GTH) void qkv_kernel(const float* __restrict__ xg,
                                                  const float* __restrict__ wq,
                                                  const float* __restrict__ wk,
                                                  const float* __restrict__ wv) {
    extern __shared__ char raw[];
    GemmSmem& sm = *reinterpret_cast<GemmSmem*>(raw);
    const float* W;
    float* outp;
    if (blockIdx.y == 0)      { W = wq; outp = g_Q; }
    else if (blockIdx.y == 1) { W = wk; outp = g_K; }
    else                      { W = wv; outp = g_V; }

    const int t = threadIdx.x;
    const int rowbase = blockIdx.x * GROWS;

    // Load x tile (128x128) and W (128x128), coalesced float4.
    #pragma unroll
    for (int it = 0; it < 16; it++) {
        int lin = t + it * GTH;          // 0..4095
        int r = lin >> 5;
        int c4 = (lin & 31) << 2;
        *reinterpret_cast<float4*>(&sm.x[r][c4]) =
            *reinterpret_cast<const float4*>(xg + (rowbase + r) * DD + c4);
        *reinterpret_cast<float4*>(&sm.w[r][c4]) =
            *reinterpret_cast<const float4*>(W + r * DD + c4);
    }
    __syncthreads();

    const int tx = t & 7;     // 8 column groups: cols tx*4 + 32*j
    const int ty = t >> 3;    // 32 row groups: rows ty + 32*i

    float acc[4][16];
    #pragma unroll
    for (int i = 0; i < 4; i++)
        #pragma unroll
        for (int j = 0; j < 16; j++) acc[i][j] = 0.f;

    for (int k = 0; k < DD; k++) {
        float xv[4];
        #pragma unroll
        for (int i = 0; i < 4; i++) xv[i] = sm.x[ty + 32 * i][k];
        float4 wv[4];
        #pragma unroll
        for (int j = 0; j < 4; j++)
            wv[j] = *reinterpret_cast<const float4*>(&sm.w[k][tx * 4 + 32 * j]);
        #pragma unroll
        for (int i = 0; i < 4; i++) {
            #pragma unroll
            for (int j = 0; j < 4; j++) {
                acc[i][4 * j + 0] += xv[i] * wv[j].x;
                acc[i][4 * j + 1] += xv[i] * wv[j].y;
                acc[i][4 * j + 2] += xv[i] * wv[j].z;
                acc[i][4 * j + 3] += xv[i] * wv[j].w;
            }
        }
    }

    #pragma unroll
    for (int i = 0; i < 4; i++) {
        int r = rowbase + ty + 32 * i;
        #pragma unroll
        for (int j = 0; j < 4; j++) {
            float4 v = make_float4(acc[i][4 * j + 0], acc[i][4 * j + 1],
                                   acc[i][4 * j + 2], acc[i][4 * j + 3]);
            *reinterpret_cast<float4*>(outp + r * DD + tx * 4 + 32 * j) = v;
        }
    }
}

// ---------------- Flash attention (online softmax) ----------------
#define BQ 64
#define BK 64
#define FTH 256
#define PADD (DD + 4)    // 132 floats/row
#define SPAD 68

struct FlashSmem {
    float Q[BQ][PADD];
    float K[BK][PADD];
    float V[BK][PADD];   // column-XOR-swizzled in float4 units
    float P[BQ][SPAD];
    float m[BQ];
    float l[BQ];
    float alpha[BQ];
};

__global__ __launch_bounds__(FTH) void flash_kernel(float* __restrict__ outp) {
    extern __shared__ char raw[];
    FlashSmem& sm = *reinterpret_cast<FlashSmem*>(raw);
    const int t = threadIdx.x;
    const int b = blockIdx.x >> 6;       // S/BQ = 64 q-tiles per batch
    const int qt = blockIdx.x & 63;
    const int qbase = b * SS + qt * BQ;
    const float scale = 0.08838834764831845f;  // 1/sqrt(128)

    // Load + pre-scale Q tile.
    #pragma unroll
    for (int it = 0; it < 8; it++) {
        int lin = t + it * FTH;
        int r = lin >> 5;
        int c4 = (lin & 31) << 2;
        float4 v = *reinterpret_cast<const float4*>(g_Q + (qbase + r) * DD + c4);
        v.x *= scale; v.y *= scale; v.z *= scale; v.w *= scale;
        *reinterpret_cast<float4*>(&sm.Q[r][c4]) = v;
    }
    if (t < BQ) { sm.m[t] = -INFINITY; sm.l[t] = 0.f; }

    float o[32];
    #pragma unroll
    for (int j = 0; j < 32; j++) o[j] = 0.f;

    const int ty = t >> 4;            // 0..15: q rows ty + 16*i
    const int tx = t & 15;            // 0..15: k rows tx + 16*j
    const int qown = t >> 2;          // 0..63: PV owner row
    const int dg4 = (t & 3) << 3;     // d chunk base in float4 units (0,8,16,24)
    __syncthreads();

    for (int kt = 0; kt < SS / BK; kt++) {
        const int kbase = b * SS + kt * BK;
        // Load K (plain) and V (XOR-swizzled columns).
        #pragma unroll
        for (int it = 0; it < 8; it++) {
            int lin = t + it * FTH;
            int r = lin >> 5;
            int c4i = lin & 31;
            int c4 = c4i << 2;
            *reinterpret_cast<float4*>(&sm.K[r][c4]) =
                *reinterpret_cast<const float4*>(g_K + (kbase + r) * DD + c4);
            int sw = (c4i ^ ((c4i >> 3) & 3)) << 2;
            *reinterpret_cast<float4*>(&sm.V[r][sw]) =
                *reinterpret_cast<const float4*>(g_V + (kbase + r) * DD + c4);
        }
        __syncthreads();

        // Scores: 4x4 register tile per thread.
        float acc[4][4];
        #pragma unroll
        for (int i = 0; i < 4; i++)
            #pragma unroll
            for (int j = 0; j < 4; j++) acc[i][j] = 0.f;

        for (int d = 0; d < DD; d += 4) {
            float4 qv[4], kv[4];
            #pragma unroll
            for (int i = 0; i < 4; i++)
                qv[i] = *reinterpret_cast<const float4*>(&sm.Q[ty + 16 * i][d]);
            #pragma unroll
            for (int j = 0; j < 4; j++)
                kv[j] = *reinterpret_cast<const float4*>(&sm.K[tx + 16 * j][d]);
            #pragma unroll
            for (int i = 0; i < 4; i++) {
                #pragma unroll
                for (int j = 0; j < 4; j++) {
                    acc[i][j] += qv[i].x * kv[j].x;
                    acc[i][j] += qv[i].y * kv[j].y;
                    acc[i][j] += qv[i].z * kv[j].z;
                    acc[i][j] += qv[i].w * kv[j].w;
                }
            }
        }
        #pragma unroll
        for (int i = 0; i < 4; i++)
            #pragma unroll
            for (int j = 0; j < 4; j++)
                sm.P[ty + 16 * i][tx + 16 * j] = acc[i][j];
        __syncthreads();

        // Online softmax: one thread per q row.
        if (t < BQ) {
            float mold = sm.m[t];
            float mx = mold;
            #pragma unroll
            for (int j = 0; j < BK; j++) mx = fmaxf(mx, sm.P[t][j]);
            float a = __expf(mold - mx);   // exp(-inf)=0 on first tile
            float ssum = 0.f;
            #pragma unroll
            for (int j = 0; j < BK; j++) {
                float p = __expf(sm.P[t][j] - mx);
                sm.P[t][j] = p;
                ssum += p;
            }
            sm.m[t] = mx;
            sm.l[t] = sm.l[t] * a + ssum;
            sm.alpha[t] = a;
        }
        __syncthreads();

        // PV accumulation: thread owns (qown, 32 dims starting at dg4*4).
        float a = sm.alpha[qown];
        #pragma unroll
        for (int j = 0; j < 32; j++) o[j] *= a;
        for (int k = 0; k < BK; k++) {
            float p = sm.P[qown][k];
            #pragma unroll
            for (int jj = 0; jj < 8; jj++) {
                int c4i = dg4 + jj;
                int sw = (c4i ^ ((c4i >> 3) & 3)) << 2;
                float4 v = *reinterpret_cast<const float4*>(&sm.V[k][sw]);
                o[jj * 4 + 0] += p * v.x;
                o[jj * 4 + 1] += p * v.y;
                o[jj * 4 + 2] += p * v.z;
                o[jj * 4 + 3] += p * v.w;
            }
        }
        __syncthreads();   // protect K/V/P before next tile's loads
    }

    const float inv = 1.f / sm.l[qown];
    const int orow = qbase + qown;
    #pragma unroll
    for (int jj = 0; jj < 8; jj++) {
        float4 v = make_float4(o[jj * 4 + 0] * inv, o[jj * 4 + 1] * inv,
                               o[jj * 4 + 2] * inv, o[jj * 4 + 3] * inv);
        *reinterpret_cast<float4*>(outp + orow * DD + (dg4 << 2) + jj * 4) = v;
    }
}

extern "C" void kernel_launch(void* const* d_in, const int* in_sizes, int n_in,
                              void* d_out, int out_size) {
    const float* x  = (const float*)d_in[0];
    // d_in[1] = token_attention_masks (int64) — unused by the reference math.
    const float* wq = (const float*)d_in[2];
    const float* wk = (const float*)d_in[3];
    const float* wv = (const float*)d_in[4];
    float* out = (float*)d_out;

    cudaFuncSetAttribute(qkv_kernel, cudaFuncAttributeMaxDynamicSharedMemorySize,
                         (int)sizeof(GemmSmem));
    cudaFuncSetAttribute(flash_kernel, cudaFuncAttributeMaxDynamicSharedMemorySize,
                         (int)sizeof(FlashSmem));

    dim3 g1((BB * SS) / GROWS, 3);
    qkv_kernel<<<g1, GTH, sizeof(GemmSmem)>>>(x, wq, wk, wv);
    flash_kernel<<<BB * (SS / BQ), FTH, sizeof(FlashSmem)>>>(out);
}

// round 5
// speedup vs baseline: 4.6185x; 4.6185x over previous
#include <cuda_runtime.h>
#include <cuda_bf16.h>
#include <math.h>
#include <stdint.h>

#define DD 128
#define SS 4096
#define BB 4

__device__ float g_Q[BB * SS * DD];
__device__ float g_K[BB * SS * DD];
__device__ float g_V[BB * SS * DD];
__device__ __nv_bfloat16 g_Qh[BB * SS * DD];
__device__ __nv_bfloat16 g_Ql[BB * SS * DD];
__device__ __nv_bfloat16 g_Kh[BB * SS * DD];
__device__ __nv_bfloat16 g_Kl[BB * SS * DD];
__device__ __nv_bfloat16 g_Vth[BB * DD * SS];   // [b*128+d][token]
__device__ __nv_bfloat16 g_Vtl[BB * DD * SS];
__device__ float g_rq[BB * SS];   // qsum per token (scaled q)
__device__ float g_rk[BB * SS];   // mean of k per token

// ---- warp MMA helpers (arch-portable PTX) ----
__device__ __forceinline__ uint32_t smem_u32(const void* p) {
    uint32_t a;
    asm("{ .reg .u64 t; cvta.to.shared.u64 t, %1; cvt.u32.u64 %0, t; }" : "=r"(a) : "l"(p));
    return a;
}
__device__ __forceinline__ void ldsm4(uint32_t* d, uint32_t addr) {
    asm volatile("ldmatrix.sync.aligned.m8n8.x4.shared.b16 {%0,%1,%2,%3}, [%4];"
                 : "=r"(d[0]), "=r"(d[1]), "=r"(d[2]), "=r"(d[3]) : "r"(addr));
}
__device__ __forceinline__ void mma16816(float* c, const uint32_t* a, const uint32_t* b) {
    asm volatile("mma.sync.aligned.m16n8k16.row.col.f32.bf16.bf16.f32 "
                 "{%0,%1,%2,%3}, {%4,%5,%6,%7}, {%8,%9}, {%0,%1,%2,%3};"
                 : "+f"(c[0]), "+f"(c[1]), "+f"(c[2]), "+f"(c[3])
                 : "r"(a[0]), "r"(a[1]), "r"(a[2]), "r"(a[3]), "r"(b[0]), "r"(b[1]));
}
__device__ __forceinline__ uint32_t pack_bf16x2(float lo, float hi) {
    uint32_t r;
    asm("cvt.rn.bf16x2.f32 %0, %1, %2;" : "=r"(r) : "f"(hi), "f"(lo));
    return r;
}
// swizzled smem offsets (16B-chunk XOR within 128B groups)
__device__ __forceinline__ uint32_t sw256(int r, int c16) {   // 256B rows (128 bf16)
    return (uint32_t)(r * 256 + (((c16 & 8) | ((c16 & 7) ^ (r & 7))) << 4));
}
__device__ __forceinline__ uint32_t sw128(int r, int c16) {   // 128B rows (64 bf16)
    return (uint32_t)(r * 128 + (((c16 ^ r) & 7) << 4));
}

// ---- QKV projection (fp32 SIMT) ----
#define GROWS 128
#define GTH 256
struct GemmSmem { float x[GROWS][DD + 4]; float w[DD][DD + 4]; };
__global__ __launch_bounds__(GTH) void qkv_kernel(const float* __restrict__ xg, const float* __restrict__ wq,
                                                  const float* __restrict__ wk, const float* __restrict__ wv) {
    extern __shared__ char raw[];
    GemmSmem& sm = *reinterpret_cast<GemmSmem*>(raw);
    const float* W; float* outp;
    if (blockIdx.y == 0)      { W = wq; outp = g_Q; }
    else if (blockIdx.y == 1) { W = wk; outp = g_K; }
    else                      { W = wv; outp = g_V; }
    const int t = threadIdx.x, rowbase = blockIdx.x * GROWS;
    #pragma unroll
    for (int it = 0; it < 16; it++) {
        int lin = t + it * GTH, r = lin >> 5, c4 = (lin & 31) << 2;
        *reinterpret_cast<float4*>(&sm.x[r][c4]) = *reinterpret_cast<const float4*>(xg + (size_t)(rowbase + r) * DD + c4);
        *reinterpret_cast<float4*>(&sm.w[r][c4]) = *reinterpret_cast<const float4*>(W + (size_t)r * DD + c4);
    }
    __syncthreads();
    const int tx = t & 7, ty = t >> 3;
    float acc[4][16];
    #pragma unroll
    for (int i = 0; i < 4; i++) {
        #pragma unroll
        for (int j = 0; j < 16; j++) acc[i][j] = 0.f;
    }
    for (int k = 0; k < DD; k++) {
        float xv[4];
        #pragma unroll
        for (int i = 0; i < 4; i++) xv[i] = sm.x[ty + 32 * i][k];
        float4 wv4[4];
        #pragma unroll
        for (int j = 0; j < 4; j++) wv4[j] = *reinterpret_cast<const float4*>(&sm.w[k][tx * 4 + 32 * j]);
        #pragma unroll
        for (int i = 0; i < 4; i++) {
            #pragma unroll
            for (int j = 0; j < 4; j++) {
                acc[i][4 * j + 0] += xv[i] * wv4[j].x;
                acc[i][4 * j + 1] += xv[i] * wv4[j].y;
                acc[i][4 * j + 2] += xv[i] * wv4[j].z;
                acc[i][4 * j + 3] += xv[i] * wv4[j].w;
            }
        }
    }
    #pragma unroll
    for (int i = 0; i < 4; i++) {
        int r = rowbase + ty + 32 * i;
        #pragma unroll
        for (int j = 0; j < 4; j++) {
            float4 v = make_float4(acc[i][4 * j], acc[i][4 * j + 1], acc[i][4 * j + 2], acc[i][4 * j + 3]);
            *reinterpret_cast<float4*>(outp + (size_t)r * DD + tx * 4 + 32 * j) = v;
        }
    }
}

// ---- prep: center + bf16-split Q,K ----
__global__ __launch_bounds__(256) void split_qk_kernel() {
    __shared__ float2 red[2][4];
    const int ty = threadIdx.y, d = threadIdx.x;
    const int token = blockIdx.x * 2 + ty;
    const int idx = token * DD + d;
    const float SCALE = 0.08838834764831845f;
    float q = g_Q[idx] * SCALE, k = g_K[idx];
    float qs = q, ks = k;
    #pragma unroll
    for (int off = 16; off; off >>= 1) {
        qs += __shfl_xor_sync(0xFFFFFFFFu, qs, off);
        ks += __shfl_xor_sync(0xFFFFFFFFu, ks, off);
    }
    if ((d & 31) == 0) red[ty][d >> 5] = make_float2(qs, ks);
    __syncthreads();
    float qsum = red[ty][0].x + red[ty][1].x + red[ty][2].x + red[ty][3].x;
    float ksum = red[ty][0].y + red[ty][1].y + red[ty][2].y + red[ty][3].y;
    float mq = qsum * (1.f / 128.f), mk = ksum * (1.f / 128.f);
    float qc = q - mq, kc = k - mk;
    __nv_bfloat16 qh = __float2bfloat16(qc), kh = __float2bfloat16(kc);
    g_Qh[idx] = qh; g_Ql[idx] = __float2bfloat16(qc - __bfloat162float(qh));
    g_Kh[idx] = kh; g_Kl[idx] = __float2bfloat16(kc - __bfloat162float(kh));
    if (d == 0) { g_rq[token] = qsum; g_rk[token] = mk; }
}

// ---- prep: transpose + bf16-split V ----
__global__ __launch_bounds__(256) void vsplit_kernel() {
    __shared__ float tile[64][68];
    const int t = threadIdx.x;
    const int tok0 = blockIdx.x * 64, db = blockIdx.y * 64;
    const int b = tok0 >> 12, s0 = tok0 & (SS - 1);
    #pragma unroll
    for (int it = 0; it < 4; it++) {
        int lin = t + it * 256, r = lin >> 4, c4 = lin & 15;
        float4 v = *reinterpret_cast<const float4*>(g_V + (size_t)(tok0 + r) * DD + db + c4 * 4);
        tile[r][c4 * 4] = v.x; tile[r][c4 * 4 + 1] = v.y; tile[r][c4 * 4 + 2] = v.z; tile[r][c4 * 4 + 3] = v.w;
    }
    __syncthreads();
    const int od = t >> 2, seg = t & 3;
    __align__(16) __nv_bfloat16 hs[16], ls[16];
    #pragma unroll
    for (int j = 0; j < 16; j++) {
        float v = tile[seg * 16 + j][od];
        __nv_bfloat16 h = __float2bfloat16(v);
        hs[j] = h; ls[j] = __float2bfloat16(v - __bfloat162float(h));
    }
    size_t ob = (size_t)(b * DD + db + od) * SS + s0 + seg * 16;
    *reinterpret_cast<uint4*>(&g_Vth[ob]) = *reinterpret_cast<uint4*>(&hs[0]);
    *reinterpret_cast<uint4*>(&g_Vth[ob + 8]) = *reinterpret_cast<uint4*>(&hs[8]);
    *reinterpret_cast<uint4*>(&g_Vtl[ob]) = *reinterpret_cast<uint4*>(&ls[0]);
    *reinterpret_cast<uint4*>(&g_Vtl[ob + 8]) = *reinterpret_cast<uint4*>(&ls[8]);
}

// ---- warp-MMA flash attention ----
#define BQ 128
#define BK 64
#define QH_OFF 0
#define QL_OFF 32768
#define KH_OFF 65536
#define KL_OFF (65536 + 16384)
#define VH_OFF (65536 + 32768)
#define VL_OFF (65536 + 49152)
#define MK_OFF (65536 + 65536)
#define FSMEM_TOTAL (MK_OFF + 256)

__global__ __launch_bounds__(256, 1) void flash_mma_kernel(float* __restrict__ outp) {
    extern __shared__ char smem[];
    const uint32_t sb = smem_u32(smem);
    float* smk = (float*)(smem + MK_OFF);
    const int t = threadIdx.x, w = t >> 5, lane = t & 31;
    const int b = blockIdx.x >> 5, qt = blockIdx.x & 31;    // 32 q-tiles per batch
    const int qtok = b * SS + qt * BQ;
    const int m0 = w * 16;
    const int g = lane >> 3, rr = lane & 7;
    // ldmatrix per-lane row/half assignments
    const int rowA = m0 + ((g & 1) << 3) + rr;  const int hA = g >> 1;   // A frags (Q)
    const int rowB8 = ((g >> 1) << 3) + rr;      const int hB = g & 1;   // B frags (K/V)

    // load Q hi/lo into swizzled smem
    #pragma unroll
    for (int it = 0; it < 8; it++) {
        int lin = t + it * 256, r = lin >> 4, c = lin & 15;
        *reinterpret_cast<uint4*>(smem + QH_OFF + sw256(r, c)) =
            *reinterpret_cast<const uint4*>(g_Qh + (size_t)(qtok + r) * DD + c * 8);
        *reinterpret_cast<uint4*>(smem + QL_OFF + sw256(r, c)) =
            *reinterpret_cast<const uint4*>(g_Ql + (size_t)(qtok + r) * DD + c * 8);
    }
    const int r0g = qtok + m0 + (lane >> 2);
    const float rq0 = g_rq[r0g], rq1 = g_rq[r0g + 8];

    float o[16][4];
    #pragma unroll
    for (int i = 0; i < 16; i++) { o[i][0] = o[i][1] = o[i][2] = o[i][3] = 0.f; }
    float mr0 = -INFINITY, mr1 = -INFINITY, lr0 = 0.f, lr1 = 0.f;
    __syncthreads();

    for (int kt = 0; kt < SS / BK; kt++) {
        const int ktok = b * SS + kt * BK;
        // load K (64x128) hi/lo and Vt (128x64) hi/lo
        #pragma unroll
        for (int it = 0; it < 4; it++) {
            int lin = t + it * 256;
            int kr = lin >> 4, kc = lin & 15;
            *reinterpret_cast<uint4*>(smem + KH_OFF + sw256(kr, kc)) =
                *reinterpret_cast<const uint4*>(g_Kh + (size_t)(ktok + kr) * DD + kc * 8);
            *reinterpret_cast<uint4*>(smem + KL_OFF + sw256(kr, kc)) =
                *reinterpret_cast<const uint4*>(g_Kl + (size_t)(ktok + kr) * DD + kc * 8);
            int vr = lin >> 3, vc = lin & 7;
            size_t vsrc = (size_t)(b * DD + vr) * SS + kt * BK + vc * 8;
            *reinterpret_cast<uint4*>(smem + VH_OFF + sw128(vr, vc)) =
                *reinterpret_cast<const uint4*>(g_Vth + vsrc);
            *reinterpret_cast<uint4*>(smem + VL_OFF + sw128(vr, vc)) =
                *reinterpret_cast<const uint4*>(g_Vtl + vsrc);
        }
        if (t < BK) smk[t] = g_rk[ktok + t];
        __syncthreads();

        // ---- S = Qc·Kc' (3-pass bf16 emulation), 16x64 per warp ----
        float S[8][4];
        #pragma unroll
        for (int i = 0; i < 8; i++) { S[i][0] = S[i][1] = S[i][2] = S[i][3] = 0.f; }
        #pragma unroll
        for (int kc = 0; kc < 8; kc++) {
            uint32_t Ah[4], Al[4];
            ldsm4(Ah, sb + QH_OFF + sw256(rowA, kc * 2 + hA));
            ldsm4(Al, sb + QL_OFF + sw256(rowA, kc * 2 + hA));
            #pragma unroll
            for (int np = 0; np < 4; np++) {
                uint32_t Bh[4], Bl[4];
                ldsm4(Bh, sb + KH_OFF + sw256(np * 16 + rowB8, kc * 2 + hB));
                ldsm4(Bl, sb + KL_OFF + sw256(np * 16 + rowB8, kc * 2 + hB));
                mma16816(S[2 * np], Ah, Bh);     mma16816(S[2 * np + 1], Ah, Bh + 2);
                mma16816(S[2 * np], Ah, Bl);     mma16816(S[2 * np + 1], Ah, Bl + 2);
                mma16816(S[2 * np], Al, Bh);     mma16816(S[2 * np + 1], Al, Bh + 2);
            }
        }

        // ---- rank-1 term + online softmax (rows fully warp-local) ----
        const int cbase = 2 * (lane & 3);
        float tm0 = -INFINITY, tm1 = -INFINITY;
        #pragma unroll
        for (int nt = 0; nt < 8; nt++) {
            float2 mk2 = *reinterpret_cast<const float2*>(&smk[nt * 8 + cbase]);
            S[nt][0] += rq0 * mk2.x; S[nt][1] += rq0 * mk2.y;
            S[nt][2] += rq1 * mk2.x; S[nt][3] += rq1 * mk2.y;
            tm0 = fmaxf(tm0, fmaxf(S[nt][0], S[nt][1]));
            tm1 = fmaxf(tm1, fmaxf(S[nt][2], S[nt][3]));
        }
        tm0 = fmaxf(tm0, __shfl_xor_sync(0xFFFFFFFFu, tm0, 1));
        tm0 = fmaxf(tm0, __shfl_xor_sync(0xFFFFFFFFu, tm0, 2));
        tm1 = fmaxf(tm1, __shfl_xor_sync(0xFFFFFFFFu, tm1, 1));
        tm1 = fmaxf(tm1, __shfl_xor_sync(0xFFFFFFFFu, tm1, 2));
        float nm0 = fmaxf(mr0, tm0), nm1 = fmaxf(mr1, tm1);
        float al0 = __expf(mr0 - nm0), al1 = __expf(mr1 - nm1);
        mr0 = nm0; mr1 = nm1;

        uint32_t PhL[8], PhH[8], PlL[8], PlH[8];
        float s0 = 0.f, s1 = 0.f;
        #pragma unroll
        for (int nt = 0; nt < 8; nt++) {
            float p0 = __expf(S[nt][0] - nm0), p1 = __expf(S[nt][1] - nm0);
            float p2 = __expf(S[nt][2] - nm1), p3 = __expf(S[nt][3] - nm1);
            s0 += p0 + p1; s1 += p2 + p3;
            float h0 = __bfloat162float(__float2bfloat16(p0));
            float h1 = __bfloat162float(__float2bfloat16(p1));
            float h2 = __bfloat162float(__float2bfloat16(p2));
            float h3 = __bfloat162float(__float2bfloat16(p3));
            PhL[nt] = pack_bf16x2(h0, h1); PhH[nt] = pack_bf16x2(h2, h3);
            PlL[nt] = pack_bf16x2(p0 - h0, p1 - h1);
            PlH[nt] = pack_bf16x2(p2 - h2, p3 - h3);
        }
        s0 += __shfl_xor_sync(0xFFFFFFFFu, s0, 1);
        s0 += __shfl_xor_sync(0xFFFFFFFFu, s0, 2);
        s1 += __shfl_xor_sync(0xFFFFFFFFu, s1, 1);
        s1 += __shfl_xor_sync(0xFFFFFFFFu, s1, 2);
        lr0 = lr0 * al0 + s0; lr1 = lr1 * al1 + s1;
        #pragma unroll
        for (int i = 0; i < 16; i++) { o[i][0] *= al0; o[i][1] *= al0; o[i][2] *= al1; o[i][3] *= al1; }

        // ---- O += P·V (3-pass), P C-frags reused directly as A-frags ----
        #pragma unroll
        for (int kc = 0; kc < 4; kc++) {
            uint32_t Aph[4] = {PhL[2 * kc], PhH[2 * kc], PhL[2 * kc + 1], PhH[2 * kc + 1]};
            uint32_t Apl[4] = {PlL[2 * kc], PlH[2 * kc], PlL[2 * kc + 1], PlH[2 * kc + 1]};
            #pragma unroll
            for (int dp = 0; dp < 8; dp++) {
                uint32_t Bh[4], Bl[4];
                ldsm4(Bh, sb + VH_OFF + sw128(dp * 16 + rowB8, kc * 2 + hB));
                ldsm4(Bl, sb + VL_OFF + sw128(dp * 16 + rowB8, kc * 2 + hB));
                mma16816(o[2 * dp], Aph, Bh);     mma16816(o[2 * dp + 1], Aph, Bh + 2);
                mma16816(o[2 * dp], Aph, Bl);     mma16816(o[2 * dp + 1], Aph, Bl + 2);
                mma16816(o[2 * dp], Apl, Bh);     mma16816(o[2 * dp + 1], Apl, Bh + 2);
            }
        }
        __syncthreads();   // protect K/V/mk before next tile's loads
    }

    const float inv0 = 1.f / lr0, inv1 = 1.f / lr1;
    #pragma unroll
    for (int nt = 0; nt < 16; nt++) {
        int col = nt * 8 + 2 * (lane & 3);
        *reinterpret_cast<float2*>(outp + (size_t)r0g * DD + col) =
            make_float2(o[nt][0] * inv0, o[nt][1] * inv0);
        *reinterpret_cast<float2*>(outp + (size_t)(r0g + 8) * DD + col) =
            make_float2(o[nt][2] * inv1, o[nt][3] * inv1);
    }
}

extern "C" void kernel_launch(void* const* d_in, const int* in_sizes, int n_in,
                              void* d_out, int out_size) {
    const float* x  = (const float*)d_in[0];
    const float* wq = (const float*)d_in[2];
    const float* wk = (const float*)d_in[3];
    const float* wv = (const float*)d_in[4];
    float* out = (float*)d_out;

    cudaFuncSetAttribute(qkv_kernel, cudaFuncAttributeMaxDynamicSharedMemorySize, (int)sizeof(GemmSmem));
    cudaFuncSetAttribute(flash_mma_kernel, cudaFuncAttributeMaxDynamicSharedMemorySize, FSMEM_TOTAL);

    dim3 g1((BB * SS) / GROWS, 3);
    qkv_kernel<<<g1, GTH, sizeof(GemmSmem)>>>(x, wq, wk, wv);
    split_qk_kernel<<<BB * SS / 2, dim3(128, 2)>>>();
    vsplit_kernel<<<dim3(BB * SS / 64, DD / 64), 256>>>();
    flash_mma_kernel<<<BB * (SS / BQ), 256, FSMEM_TOTAL>>>(out);
}

// round 6
// speedup vs baseline: 5.1054x; 1.1054x over previous
#include <cuda_runtime.h>
#include <cuda_bf16.h>
#include <math.h>
#include <stdint.h>

#define DD 128
#define SS 4096
#define BB 4

__device__ float g_Q[BB * SS * DD];
__device__ float g_K[BB * SS * DD];
__device__ float g_V[BB * SS * DD];
__device__ __nv_bfloat16 g_Qh[BB * SS * DD];
__device__ __nv_bfloat16 g_Ql[BB * SS * DD];
__device__ __nv_bfloat16 g_Kh[BB * SS * DD];
__device__ __nv_bfloat16 g_Kl[BB * SS * DD];
__device__ __nv_bfloat16 g_Vth[BB * DD * SS];   // [b*128+d][token]
__device__ __nv_bfloat16 g_Vtl[BB * DD * SS];
__device__ float g_rq[BB * SS];   // qsum per token (scaled q)
__device__ float g_rk[BB * SS];   // mean of k per token

// ---- PTX helpers (arch-portable) ----
__device__ __forceinline__ uint32_t smem_u32(const void* p) {
    uint32_t a;
    asm("{ .reg .u64 t; cvta.to.shared.u64 t, %1; cvt.u32.u64 %0, t; }" : "=r"(a) : "l"(p));
    return a;
}
__device__ __forceinline__ void ldsm4(uint32_t* d, uint32_t addr) {
    asm volatile("ldmatrix.sync.aligned.m8n8.x4.shared.b16 {%0,%1,%2,%3}, [%4];"
                 : "=r"(d[0]), "=r"(d[1]), "=r"(d[2]), "=r"(d[3]) : "r"(addr));
}
__device__ __forceinline__ void mma16816(float* c, const uint32_t* a, const uint32_t* b) {
    asm volatile("mma.sync.aligned.m16n8k16.row.col.f32.bf16.bf16.f32 "
                 "{%0,%1,%2,%3}, {%4,%5,%6,%7}, {%8,%9}, {%0,%1,%2,%3};"
                 : "+f"(c[0]), "+f"(c[1]), "+f"(c[2]), "+f"(c[3])
                 : "r"(a[0]), "r"(a[1]), "r"(a[2]), "r"(a[3]), "r"(b[0]), "r"(b[1]));
}
__device__ __forceinline__ uint32_t pack_bf16x2(float lo, float hi) {
    uint32_t r;
    asm("cvt.rn.bf16x2.f32 %0, %1, %2;" : "=r"(r) : "f"(hi), "f"(lo));
    return r;
}
__device__ __forceinline__ void cpasync16(uint32_t s, const void* g) {
    asm volatile("cp.async.cg.shared.global [%0], [%1], 16;" :: "r"(s), "l"(g));
}
#define CP_COMMIT() asm volatile("cp.async.commit_group;" ::: "memory")
#define CP_WAIT0()  asm volatile("cp.async.wait_group 0;" ::: "memory")
#define CP_WAIT1()  asm volatile("cp.async.wait_group 1;" ::: "memory")

// swizzled smem offsets (16B-chunk XOR within 128B groups)
__device__ __forceinline__ uint32_t sw256(int r, int c16) {   // 256B rows (128 bf16)
    return (uint32_t)(r * 256 + (((c16 & 8) | ((c16 & 7) ^ (r & 7))) << 4));
}
__device__ __forceinline__ uint32_t sw128(int r, int c16) {   // 128B rows (64 bf16)
    return (uint32_t)(r * 128 + (((c16 ^ r) & 7) << 4));
}

// ---- QKV projection (fp32 SIMT) ----
#define GROWS 128
#define GTH 256
struct GemmSmem { float x[GROWS][DD + 4]; float w[DD][DD + 4]; };
__global__ __launch_bounds__(GTH) void qkv_kernel(const float* __restrict__ xg, const float* __restrict__ wq,
                                                  const float* __restrict__ wk, const float* __restrict__ wv) {
    extern __shared__ char raw[];
    GemmSmem& sm = *reinterpret_cast<GemmSmem*>(raw);
    const float* W; float* outp;
    if (blockIdx.y == 0)      { W = wq; outp = g_Q; }
    else if (blockIdx.y == 1) { W = wk; outp = g_K; }
    else                      { W = wv; outp = g_V; }
    const int t = threadIdx.x, rowbase = blockIdx.x * GROWS;
    #pragma unroll
    for (int it = 0; it < 16; it++) {
        int lin = t + it * GTH, r = lin >> 5, c4 = (lin & 31) << 2;
        *reinterpret_cast<float4*>(&sm.x[r][c4]) = *reinterpret_cast<const float4*>(xg + (size_t)(rowbase + r) * DD + c4);
        *reinterpret_cast<float4*>(&sm.w[r][c4]) = *reinterpret_cast<const float4*>(W + (size_t)r * DD + c4);
    }
    __syncthreads();
    const int tx = t & 7, ty = t >> 3;
    float acc[4][16];
    #pragma unroll
    for (int i = 0; i < 4; i++) {
        #pragma unroll
        for (int j = 0; j < 16; j++) acc[i][j] = 0.f;
    }
    for (int k = 0; k < DD; k++) {
        float xv[4];
        #pragma unroll
        for (int i = 0; i < 4; i++) xv[i] = sm.x[ty + 32 * i][k];
        float4 wv4[4];
        #pragma unroll
        for (int j = 0; j < 4; j++) wv4[j] = *reinterpret_cast<const float4*>(&sm.w[k][tx * 4 + 32 * j]);
        #pragma unroll
        for (int i = 0; i < 4; i++) {
            #pragma unroll
            for (int j = 0; j < 4; j++) {
                acc[i][4 * j + 0] += xv[i] * wv4[j].x;
                acc[i][4 * j + 1] += xv[i] * wv4[j].y;
                acc[i][4 * j + 2] += xv[i] * wv4[j].z;
                acc[i][4 * j + 3] += xv[i] * wv4[j].w;
            }
        }
    }
    #pragma unroll
    for (int i = 0; i < 4; i++) {
        int r = rowbase + ty + 32 * i;
        #pragma unroll
        for (int j = 0; j < 4; j++) {
            float4 v = make_float4(acc[i][4 * j], acc[i][4 * j + 1], acc[i][4 * j + 2], acc[i][4 * j + 3]);
            *reinterpret_cast<float4*>(outp + (size_t)r * DD + tx * 4 + 32 * j) = v;
        }
    }
}

// ---- prep: center + bf16-split Q,K ----
__global__ __launch_bounds__(256) void split_qk_kernel() {
    __shared__ float2 red[2][4];
    const int ty = threadIdx.y, d = threadIdx.x;
    const int token = blockIdx.x * 2 + ty;
    const int idx = token * DD + d;
    const float SCALE = 0.08838834764831845f;
    float q = g_Q[idx] * SCALE, k = g_K[idx];
    float qs = q, ks = k;
    #pragma unroll
    for (int off = 16; off; off >>= 1) {
        qs += __shfl_xor_sync(0xFFFFFFFFu, qs, off);
        ks += __shfl_xor_sync(0xFFFFFFFFu, ks, off);
    }
    if ((d & 31) == 0) red[ty][d >> 5] = make_float2(qs, ks);
    __syncthreads();
    float qsum = red[ty][0].x + red[ty][1].x + red[ty][2].x + red[ty][3].x;
    float ksum = red[ty][0].y + red[ty][1].y + red[ty][2].y + red[ty][3].y;
    float mq = qsum * (1.f / 128.f), mk = ksum * (1.f / 128.f);
    float qc = q - mq, kc = k - mk;
    __nv_bfloat16 qh = __float2bfloat16(qc), kh = __float2bfloat16(kc);
    g_Qh[idx] = qh; g_Ql[idx] = __float2bfloat16(qc - __bfloat162float(qh));
    g_Kh[idx] = kh; g_Kl[idx] = __float2bfloat16(kc - __bfloat162float(kh));
    if (d == 0) { g_rq[token] = qsum; g_rk[token] = mk; }
}

// ---- prep: transpose + bf16-split V ----
__global__ __launch_bounds__(256) void vsplit_kernel() {
    __shared__ float tile[64][68];
    const int t = threadIdx.x;
    const int tok0 = blockIdx.x * 64, db = blockIdx.y * 64;
    const int b = tok0 >> 12, s0 = tok0 & (SS - 1);
    #pragma unroll
    for (int it = 0; it < 4; it++) {
        int lin = t + it * 256, r = lin >> 4, c4 = lin & 15;
        float4 v = *reinterpret_cast<const float4*>(g_V + (size_t)(tok0 + r) * DD + db + c4 * 4);
        tile[r][c4 * 4] = v.x; tile[r][c4 * 4 + 1] = v.y; tile[r][c4 * 4 + 2] = v.z; tile[r][c4 * 4 + 3] = v.w;
    }
    __syncthreads();
    const int od = t >> 2, seg = t & 3;
    __align__(16) __nv_bfloat16 hs[16], ls[16];
    #pragma unroll
    for (int j = 0; j < 16; j++) {
        float v = tile[seg * 16 + j][od];
        __nv_bfloat16 h = __float2bfloat16(v);
        hs[j] = h; ls[j] = __float2bfloat16(v - __bfloat162float(h));
    }
    size_t ob = (size_t)(b * DD + db + od) * SS + s0 + seg * 16;
    *reinterpret_cast<uint4*>(&g_Vth[ob]) = *reinterpret_cast<uint4*>(&hs[0]);
    *reinterpret_cast<uint4*>(&g_Vth[ob + 8]) = *reinterpret_cast<uint4*>(&hs[8]);
    *reinterpret_cast<uint4*>(&g_Vtl[ob]) = *reinterpret_cast<uint4*>(&ls[0]);
    *reinterpret_cast<uint4*>(&g_Vtl[ob + 8]) = *reinterpret_cast<uint4*>(&ls[8]);
}

// ---- warp-MMA flash attention, cp.async double-buffered ----
#define BQ 128
#define BK 64
#define QH_OFF 0
#define QL_OFF 32768
#define ST_OFF 65536
#define STAGE  65536
#define KH_S 0
#define KL_S 16384
#define VH_S 32768
#define VL_S 49152
#define MK_OFF (ST_OFF + 2 * STAGE)
#define FSMEM_TOTAL (MK_OFF + 512)
#define NT (SS / BK)

__global__ __launch_bounds__(256, 1) void flash_mma_kernel(float* __restrict__ outp) {
    extern __shared__ char smem[];
    const uint32_t sb = smem_u32(smem);
    const int t = threadIdx.x, w = t >> 5, lane = t & 31;
    const int b = blockIdx.x >> 5, qt = blockIdx.x & 31;    // 32 q-tiles per batch
    const int qtok = b * SS + qt * BQ;
    const int m0 = w * 16;
    const int g = lane >> 3, rr = lane & 7;
    const int rowA = m0 + ((g & 1) << 3) + rr;  const int hA = g >> 1;   // A frags (Q)
    const int rowB8 = ((g >> 1) << 3) + rr;      const int hB = g & 1;   // B frags (K/V)

    // load Q hi/lo into swizzled smem (plain loads, one-time)
    #pragma unroll
    for (int it = 0; it < 8; it++) {
        int lin = t + it * 256, r = lin >> 4, c = lin & 15;
        *reinterpret_cast<uint4*>(smem + QH_OFF + sw256(r, c)) =
            *reinterpret_cast<const uint4*>(g_Qh + (size_t)(qtok + r) * DD + c * 8);
        *reinterpret_cast<uint4*>(smem + QL_OFF + sw256(r, c)) =
            *reinterpret_cast<const uint4*>(g_Ql + (size_t)(qtok + r) * DD + c * 8);
    }
    const int r0g = qtok + m0 + (lane >> 2);
    const float rq0 = g_rq[r0g], rq1 = g_rq[r0g + 8];

    // stage-issue helper (cp.async, 16 chunks per thread per stage)
    auto issue_stage = [&](int kt) {
        const int st = kt & 1;
        const uint32_t base = sb + ST_OFF + st * STAGE;
        const int ktok = b * SS + kt * BK;
        #pragma unroll
        for (int it = 0; it < 4; it++) {
            int lin = t + it * 256;
            int kr = lin >> 4, kc = lin & 15;
            cpasync16(base + KH_S + sw256(kr, kc), g_Kh + (size_t)(ktok + kr) * DD + kc * 8);
            cpasync16(base + KL_S + sw256(kr, kc), g_Kl + (size_t)(ktok + kr) * DD + kc * 8);
            int vr = lin >> 3, vc = lin & 7;
            size_t vsrc = (size_t)(b * DD + vr) * SS + kt * BK + vc * 8;
            cpasync16(base + VH_S + sw128(vr, vc), g_Vth + vsrc);
            cpasync16(base + VL_S + sw128(vr, vc), g_Vtl + vsrc);
        }
        if (t < 16) cpasync16(sb + MK_OFF + st * 256 + t * 16, g_rk + ktok + t * 4);
        CP_COMMIT();
    };

    float o[16][4];
    #pragma unroll
    for (int i = 0; i < 16; i++) { o[i][0] = o[i][1] = o[i][2] = o[i][3] = 0.f; }
    float mr0 = -INFINITY, mr1 = -INFINITY, lr0 = 0.f, lr1 = 0.f;

    issue_stage(0);
    __syncthreads();   // Q tile visible to all warps

    for (int kt = 0; kt < NT; kt++) {
        const int st = kt & 1;
        const uint32_t base = sb + ST_OFF + st * STAGE;
        const float* smk = (const float*)(smem + MK_OFF + st * 256);
        if (kt + 1 < NT) { issue_stage(kt + 1); CP_WAIT1(); }
        else             { CP_WAIT0(); }
        __syncthreads();   // stage kt data visible to all warps

        // ---- S = Qc·Kc' (3-pass bf16 emulation), 16x64 per warp ----
        float S[8][4];
        #pragma unroll
        for (int i = 0; i < 8; i++) { S[i][0] = S[i][1] = S[i][2] = S[i][3] = 0.f; }
        #pragma unroll
        for (int kc = 0; kc < 8; kc++) {
            uint32_t Ah[4], Al[4];
            ldsm4(Ah, sb + QH_OFF + sw256(rowA, kc * 2 + hA));
            ldsm4(Al, sb + QL_OFF + sw256(rowA, kc * 2 + hA));
            #pragma unroll
            for (int np = 0; np < 4; np++) {
                uint32_t Bh[4], Bl[4];
                ldsm4(Bh, base + KH_S + sw256(np * 16 + rowB8, kc * 2 + hB));
                ldsm4(Bl, base + KL_S + sw256(np * 16 + rowB8, kc * 2 + hB));
                mma16816(S[2 * np], Ah, Bh);     mma16816(S[2 * np + 1], Ah, Bh + 2);
                mma16816(S[2 * np], Ah, Bl);     mma16816(S[2 * np + 1], Ah, Bl + 2);
                mma16816(S[2 * np], Al, Bh);     mma16816(S[2 * np + 1], Al, Bh + 2);
            }
        }

        // ---- rank-1 term + online softmax (rows fully warp-local) ----
        const int cbase = 2 * (lane & 3);
        float tm0 = -INFINITY, tm1 = -INFINITY;
        #pragma unroll
        for (int nt = 0; nt < 8; nt++) {
            float2 mk2 = *reinterpret_cast<const float2*>(&smk[nt * 8 + cbase]);
            S[nt][0] += rq0 * mk2.x; S[nt][1] += rq0 * mk2.y;
            S[nt][2] += rq1 * mk2.x; S[nt][3] += rq1 * mk2.y;
            tm0 = fmaxf(tm0, fmaxf(S[nt][0], S[nt][1]));
            tm1 = fmaxf(tm1, fmaxf(S[nt][2], S[nt][3]));
        }
        tm0 = fmaxf(tm0, __shfl_xor_sync(0xFFFFFFFFu, tm0, 1));
        tm0 = fmaxf(tm0, __shfl_xor_sync(0xFFFFFFFFu, tm0, 2));
        tm1 = fmaxf(tm1, __shfl_xor_sync(0xFFFFFFFFu, tm1, 1));
        tm1 = fmaxf(tm1, __shfl_xor_sync(0xFFFFFFFFu, tm1, 2));
        float nm0 = fmaxf(mr0, tm0), nm1 = fmaxf(mr1, tm1);
        float al0 = __expf(mr0 - nm0), al1 = __expf(mr1 - nm1);
        mr0 = nm0; mr1 = nm1;

        uint32_t PhL[8], PhH[8], PlL[8], PlH[8];
        float s0 = 0.f, s1 = 0.f;
        #pragma unroll
        for (int nt = 0; nt < 8; nt++) {
            float p0 = __expf(S[nt][0] - nm0), p1 = __expf(S[nt][1] - nm0);
            float p2 = __expf(S[nt][2] - nm1), p3 = __expf(S[nt][3] - nm1);
            s0 += p0 + p1; s1 += p2 + p3;
            float h0 = __bfloat162float(__float2bfloat16(p0));
            float h1 = __bfloat162float(__float2bfloat16(p1));
            float h2 = __bfloat162float(__float2bfloat16(p2));
            float h3 = __bfloat162float(__float2bfloat16(p3));
            PhL[nt] = pack_bf16x2(h0, h1); PhH[nt] = pack_bf16x2(h2, h3);
            PlL[nt] = pack_bf16x2(p0 - h0, p1 - h1);
            PlH[nt] = pack_bf16x2(p2 - h2, p3 - h3);
        }
        s0 += __shfl_xor_sync(0xFFFFFFFFu, s0, 1);
        s0 += __shfl_xor_sync(0xFFFFFFFFu, s0, 2);
        s1 += __shfl_xor_sync(0xFFFFFFFFu, s1, 1);
        s1 += __shfl_xor_sync(0xFFFFFFFFu, s1, 2);
        lr0 = lr0 * al0 + s0; lr1 = lr1 * al1 + s1;
        #pragma unroll
        for (int i = 0; i < 16; i++) { o[i][0] *= al0; o[i][1] *= al0; o[i][2] *= al1; o[i][3] *= al1; }

        // ---- O += P·V (3-pass), P C-frags reused directly as A-frags ----
        #pragma unroll
        for (int kc = 0; kc < 4; kc++) {
            uint32_t Aph[4] = {PhL[2 * kc], PhH[2 * kc], PhL[2 * kc + 1], PhH[2 * kc + 1]};
            uint32_t Apl[4] = {PlL[2 * kc], PlH[2 * kc], PlL[2 * kc + 1], PlH[2 * kc + 1]};
            #pragma unroll
            for (int dp = 0; dp < 8; dp++) {
                uint32_t Bh[4], Bl[4];
                ldsm4(Bh, base + VH_S + sw128(dp * 16 + rowB8, kc * 2 + hB));
                ldsm4(Bl, base + VL_S + sw128(dp * 16 + rowB8, kc * 2 + hB));
                mma16816(o[2 * dp], Aph, Bh);     mma16816(o[2 * dp + 1], Aph, Bh + 2);
                mma16816(o[2 * dp], Aph, Bl);     mma16816(o[2 * dp + 1], Aph, Bl + 2);
                mma16816(o[2 * dp], Apl, Bh);     mma16816(o[2 * dp + 1], Apl, Bh + 2);
            }
        }
        __syncthreads();   // all reads of stage kt done before it is overwritten
    }

    const float inv0 = 1.f / lr0, inv1 = 1.f / lr1;
    #pragma unroll
    for (int nt = 0; nt < 16; nt++) {
        int col = nt * 8 + 2 * (lane & 3);
        *reinterpret_cast<float2*>(outp + (size_t)r0g * DD + col) =
            make_float2(o[nt][0] * inv0, o[nt][1] * inv0);
        *reinterpret_cast<float2*>(outp + (size_t)(r0g + 8) * DD + col) =
            make_float2(o[nt][2] * inv1, o[nt][3] * inv1);
    }
}

extern "C" void kernel_launch(void* const* d_in, const int* in_sizes, int n_in,
                              void* d_out, int out_size) {
    const float* x  = (const float*)d_in[0];
    const float* wq = (const float*)d_in[2];
    const float* wk = (const float*)d_in[3];
    const float* wv = (const float*)d_in[4];
    float* out = (float*)d_out;

    cudaFuncSetAttribute(qkv_kernel, cudaFuncAttributeMaxDynamicSharedMemorySize, (int)sizeof(GemmSmem));
    cudaFuncSetAttribute(flash_mma_kernel, cudaFuncAttributeMaxDynamicSharedMemorySize, FSMEM_TOTAL);

    dim3 g1((BB * SS) / GROWS, 3);
    qkv_kernel<<<g1, GTH, sizeof(GemmSmem)>>>(x, wq, wk, wv);
    split_qk_kernel<<<BB * SS / 2, dim3(128, 2)>>>();
    vsplit_kernel<<<dim3(BB * SS / 64, DD / 64), 256>>>();
    flash_mma_kernel<<<BB * (SS / BQ), 256, FSMEM_TOTAL>>>(out);
}

// round 7
// speedup vs baseline: 5.5264x; 1.0824x over previous
#include <cuda_runtime.h>
#include <cuda_bf16.h>
#include <cuda_fp16.h>
#include <math.h>
#include <stdint.h>

#define DD 128
#define SS 4096
#define BB 4

__device__ __nv_bfloat16 g_Qh[BB * SS * DD];
__device__ __nv_bfloat16 g_Ql[BB * SS * DD];
__device__ __nv_bfloat16 g_Kh[BB * SS * DD];
__device__ __nv_bfloat16 g_Kl[BB * SS * DD];
__device__ __nv_bfloat16 g_Vth[BB * DD * SS];   // [b*128+d][token]
__device__ __nv_bfloat16 g_Vtl[BB * DD * SS];
__device__ float g_rq[BB * SS];   // qsum per token (scaled q)
__device__ float g_rk[BB * SS];   // mean of k per token

// ---- PTX helpers (arch-portable) ----
__device__ __forceinline__ uint32_t smem_u32(const void* p) {
    uint32_t a;
    asm("{ .reg .u64 t; cvta.to.shared.u64 t, %1; cvt.u32.u64 %0, t; }" : "=r"(a) : "l"(p));
    return a;
}
__device__ __forceinline__ void ldsm4(uint32_t* d, uint32_t addr) {
    asm volatile("ldmatrix.sync.aligned.m8n8.x4.shared.b16 {%0,%1,%2,%3}, [%4];"
                 : "=r"(d[0]), "=r"(d[1]), "=r"(d[2]), "=r"(d[3]) : "r"(addr));
}
__device__ __forceinline__ void mma16816(float* c, const uint32_t* a, const uint32_t* b) {
    asm volatile("mma.sync.aligned.m16n8k16.row.col.f32.bf16.bf16.f32 "
                 "{%0,%1,%2,%3}, {%4,%5,%6,%7}, {%8,%9}, {%0,%1,%2,%3};"
                 : "+f"(c[0]), "+f"(c[1]), "+f"(c[2]), "+f"(c[3])
                 : "r"(a[0]), "r"(a[1]), "r"(a[2]), "r"(a[3]), "r"(b[0]), "r"(b[1]));
}
__device__ __forceinline__ void mma16816h(float* c, const uint32_t* a, const uint32_t* b) {
    asm volatile("mma.sync.aligned.m16n8k16.row.col.f32.f16.f16.f32 "
                 "{%0,%1,%2,%3}, {%4,%5,%6,%7}, {%8,%9}, {%0,%1,%2,%3};"
                 : "+f"(c[0]), "+f"(c[1]), "+f"(c[2]), "+f"(c[3])
                 : "r"(a[0]), "r"(a[1]), "r"(a[2]), "r"(a[3]), "r"(b[0]), "r"(b[1]));
}
__device__ __forceinline__ uint32_t pack_bf16x2(float lo, float hi) {
    uint32_t r;
    asm("cvt.rn.bf16x2.f32 %0, %1, %2;" : "=r"(r) : "f"(hi), "f"(lo));
    return r;
}
__device__ __forceinline__ void cpasync16(uint32_t s, const void* g) {
    asm volatile("cp.async.cg.shared.global [%0], [%1], 16;" :: "r"(s), "l"(g));
}
#define CP_COMMIT() asm volatile("cp.async.commit_group;" ::: "memory")
#define CP_WAIT0()  asm volatile("cp.async.wait_group 0;" ::: "memory")
#define CP_WAIT1()  asm volatile("cp.async.wait_group 1;" ::: "memory")

// swizzled smem offsets (16B-chunk XOR within 128B groups)
__device__ __forceinline__ uint32_t sw256(int r, int c16) {   // 256B rows (128 x 16-bit)
    return (uint32_t)(r * 256 + (((c16 & 8) | ((c16 & 7) ^ (r & 7))) << 4));
}
__device__ __forceinline__ uint32_t sw128(int r, int c16) {   // 128B rows (64 x 16-bit)
    return (uint32_t)(r * 128 + (((c16 ^ r) & 7) << 4));
}

// ================= fused QKV projection + center/split/transpose =============
// grid (128 tiles, 3 proj), 256 threads.  C = x_tile(128x128) @ W (fp16 hi/lo,
// 3-pass MMA, fp32 accum).  Epilogue: Q/K -> rowsum, center, bf16 split;
// V -> transpose + bf16 split.
#define PA_H 0
#define PA_L 32768
#define PB_H 65536
#define PB_L 98304
#define PC_OFF 131072                 // fp32 tile [128][132]
#define PR_OFF (PC_OFF + 128 * 132 * 4)
#define PSMEM  (PR_OFF + 1024)

__global__ __launch_bounds__(256, 1) void proj_kernel(const float* __restrict__ xg,
                                                      const float* __restrict__ wq,
                                                      const float* __restrict__ wk,
                                                      const float* __restrict__ wv) {
    extern __shared__ char smem[];
    const uint32_t sb = smem_u32(smem);
    float* tileC = (float*)(smem + PC_OFF);
    float* rmean = (float*)(smem + PR_OFF);
    const int t = threadIdx.x, w = t >> 5, lane = t & 31;
    const int tile = blockIdx.x, proj = blockIdx.y;
    const int tok0 = tile * 128;
    const int b = tok0 >> 12, s0 = tok0 & (SS - 1);
    const float* W = (proj == 0) ? wq : (proj == 1) ? wk : wv;
    const float SCALE = 0.08838834764831845f;

    // ---- load x tile -> fp16 h/l smem (swizzled) ----
    #pragma unroll
    for (int it = 0; it < 8; it++) {
        int lin = t + it * 256;             // 2048 16B-chunks
        int r = lin >> 4, c16 = lin & 15;
        const float* src = xg + (size_t)(tok0 + r) * DD + c16 * 8;
        float4 v0 = *reinterpret_cast<const float4*>(src);
        float4 v1 = *reinterpret_cast<const float4*>(src + 4);
        __half2 h0 = __floats2half2_rn(v0.x, v0.y), h1 = __floats2half2_rn(v0.z, v0.w);
        __half2 h2 = __floats2half2_rn(v1.x, v1.y), h3 = __floats2half2_rn(v1.z, v1.w);
        float2 f0 = __half22float2(h0), f1 = __half22float2(h1);
        float2 f2 = __half22float2(h2), f3 = __half22float2(h3);
        __half2 l0 = __floats2half2_rn(v0.x - f0.x, v0.y - f0.y);
        __half2 l1 = __floats2half2_rn(v0.z - f1.x, v0.w - f1.y);
        __half2 l2 = __floats2half2_rn(v1.x - f2.x, v1.y - f2.y);
        __half2 l3 = __floats2half2_rn(v1.z - f3.x, v1.w - f3.y);
        uint4 hv = make_uint4(*(uint32_t*)&h0, *(uint32_t*)&h1, *(uint32_t*)&h2, *(uint32_t*)&h3);
        uint4 lv = make_uint4(*(uint32_t*)&l0, *(uint32_t*)&l1, *(uint32_t*)&l2, *(uint32_t*)&l3);
        *reinterpret_cast<uint4*>(smem + PA_H + sw256(r, c16)) = hv;
        *reinterpret_cast<uint4*>(smem + PA_L + sw256(r, c16)) = lv;
    }
    // ---- load W -> transposed fp16 h/l smem Wt[e][d] ----
    #pragma unroll
    for (int it = 0; it < 8; it++) {
        int lin = t + it * 256;
        int d = lin >> 4, c16 = lin & 15;
        const float* src = W + (size_t)d * DD + c16 * 8;
        float wv[8];
        *reinterpret_cast<float4*>(wv) = *reinterpret_cast<const float4*>(src);
        *reinterpret_cast<float4*>(wv + 4) = *reinterpret_cast<const float4*>(src + 4);
        #pragma unroll
        for (int j = 0; j < 8; j++) {
            int e = c16 * 8 + j;
            __half h = __float2half_rn(wv[j]);
            __half l = __float2half_rn(wv[j] - __half2float(h));
            uint32_t off = sw256(e, d >> 3) + (d & 7) * 2;
            *reinterpret_cast<__half*>(smem + PB_H + off) = h;
            *reinterpret_cast<__half*>(smem + PB_L + off) = l;
        }
    }
    __syncthreads();

    // ---- 3-pass fp16 MMA: C = Ah*Bh + Ah*Bl + Al*Bh ----
    const int m0 = w * 16;
    const int g = lane >> 3, rr = lane & 7;
    const int rowA = m0 + ((g & 1) << 3) + rr;  const int hA = g >> 1;
    const int rowB8 = ((g >> 1) << 3) + rr;      const int hB = g & 1;

    float C[16][4];
    #pragma unroll
    for (int i = 0; i < 16; i++) { C[i][0] = C[i][1] = C[i][2] = C[i][3] = 0.f; }
    #pragma unroll
    for (int kc = 0; kc < 8; kc++) {
        uint32_t Ah[4], Al[4];
        ldsm4(Ah, sb + PA_H + sw256(rowA, kc * 2 + hA));
        ldsm4(Al, sb + PA_L + sw256(rowA, kc * 2 + hA));
        #pragma unroll
        for (int np = 0; np < 8; np++) {
            uint32_t Bh[4], Bl[4];
            ldsm4(Bh, sb + PB_H + sw256(np * 16 + rowB8, kc * 2 + hB));
            ldsm4(Bl, sb + PB_L + sw256(np * 16 + rowB8, kc * 2 + hB));
            mma16816h(C[2 * np], Ah, Bh);     mma16816h(C[2 * np + 1], Ah, Bh + 2);
            mma16816h(C[2 * np], Ah, Bl);     mma16816h(C[2 * np + 1], Ah, Bl + 2);
            mma16816h(C[2 * np], Al, Bh);     mma16816h(C[2 * np + 1], Al, Bh + 2);
        }
    }
    __syncthreads();   // A/B smem dead; now write C tile (aliasing none)

    const int lr = lane >> 2, lc = 2 * (lane & 3);
    #pragma unroll
    for (int np = 0; np < 8; np++) {
        #pragma unroll
        for (int nn = 0; nn < 2; nn++) {
            int c0 = np * 16 + nn * 8 + lc;
            float* p0 = tileC + (m0 + lr) * 132 + c0;
            float* p1 = tileC + (m0 + lr + 8) * 132 + c0;
            p0[0] = C[np * 2 + nn][0]; p0[1] = C[np * 2 + nn][1];
            p1[0] = C[np * 2 + nn][2]; p1[1] = C[np * 2 + nn][3];
        }
    }
    __syncthreads();

    if (proj < 2) {
        // row sums (2 threads per row)
        const int r = t >> 1, part = t & 1;
        float s = 0.f;
        #pragma unroll
        for (int j = 0; j < 16; j++) {
            float4 v = *reinterpret_cast<float4*>(tileC + r * 132 + part * 64 + j * 4);
            s += v.x + v.y + v.z + v.w;
        }
        s += __shfl_xor_sync(0xFFFFFFFFu, s, 1);
        if (proj == 0) {
            float rq = s * SCALE;
            if (part == 0) { rmean[r] = rq * (1.f / 128.f); g_rq[tok0 + r] = rq; }
        } else {
            float mk = s * (1.f / 128.f);
            if (part == 0) { rmean[r] = mk; g_rk[tok0 + r] = mk; }
        }
        __syncthreads();
        const float mu = rmean[r];
        __nv_bfloat16* gh = (proj == 0) ? g_Qh : g_Kh;
        __nv_bfloat16* gl = (proj == 0) ? g_Ql : g_Kl;
        const float fac = (proj == 0) ? SCALE : 1.f;
        #pragma unroll
        for (int j8 = 0; j8 < 8; j8++) {
            int c = part * 64 + j8 * 8;
            __align__(16) __nv_bfloat16 hs[8], ls[8];
            #pragma unroll
            for (int j = 0; j < 8; j++) {
                float v = tileC[r * 132 + c + j] * fac - mu;
                __nv_bfloat16 h = __float2bfloat16(v);
                hs[j] = h; ls[j] = __float2bfloat16(v - __bfloat162float(h));
            }
            size_t ob = (size_t)(tok0 + r) * DD + c;
            *reinterpret_cast<uint4*>(&gh[ob]) = *reinterpret_cast<uint4*>(hs);
            *reinterpret_cast<uint4*>(&gl[ob]) = *reinterpret_cast<uint4*>(ls);
        }
    } else {
        // V: transpose + split.  thread: dim od, token half seg.
        const int od = t >> 1, seg = t & 1;
        #pragma unroll
        for (int j8 = 0; j8 < 8; j8++) {
            __align__(16) __nv_bfloat16 hs[8], ls[8];
            #pragma unroll
            for (int j = 0; j < 8; j++) {
                float v = tileC[(seg * 64 + j8 * 8 + j) * 132 + od];
                __nv_bfloat16 h = __float2bfloat16(v);
                hs[j] = h; ls[j] = __float2bfloat16(v - __bfloat162float(h));
            }
            size_t ob = (size_t)(b * DD + od) * SS + s0 + seg * 64 + j8 * 8;
            *reinterpret_cast<uint4*>(&g_Vth[ob]) = *reinterpret_cast<uint4*>(hs);
            *reinterpret_cast<uint4*>(&g_Vtl[ob]) = *reinterpret_cast<uint4*>(ls);
        }
    }
}

// ---- warp-MMA flash attention, cp.async double-buffered ----
#define BQ 128
#define BK 64
#define QH_OFF 0
#define QL_OFF 32768
#define ST_OFF 65536
#define STAGE  65536
#define KH_S 0
#define KL_S 16384
#define VH_S 32768
#define VL_S 49152
#define MK_OFF (ST_OFF + 2 * STAGE)
#define FSMEM_TOTAL (MK_OFF + 512)
#define NT (SS / BK)

__global__ __launch_bounds__(256, 1) void flash_mma_kernel(float* __restrict__ outp) {
    extern __shared__ char smem[];
    const uint32_t sb = smem_u32(smem);
    const int t = threadIdx.x, w = t >> 5, lane = t & 31;
    const int b = blockIdx.x >> 5, qt = blockIdx.x & 31;
    const int qtok = b * SS + qt * BQ;
    const int m0 = w * 16;
    const int g = lane >> 3, rr = lane & 7;
    const int rowA = m0 + ((g & 1) << 3) + rr;  const int hA = g >> 1;
    const int rowB8 = ((g >> 1) << 3) + rr;      const int hB = g & 1;

    #pragma unroll
    for (int it = 0; it < 8; it++) {
        int lin = t + it * 256, r = lin >> 4, c = lin & 15;
        *reinterpret_cast<uint4*>(smem + QH_OFF + sw256(r, c)) =
            *reinterpret_cast<const uint4*>(g_Qh + (size_t)(qtok + r) * DD + c * 8);
        *reinterpret_cast<uint4*>(smem + QL_OFF + sw256(r, c)) =
            *reinterpret_cast<const uint4*>(g_Ql + (size_t)(qtok + r) * DD + c * 8);
    }
    const int r0g = qtok + m0 + (lane >> 2);
    const float rq0 = g_rq[r0g], rq1 = g_rq[r0g + 8];

    auto issue_stage = [&](int kt) {
        const int st = kt & 1;
        const uint32_t base = sb + ST_OFF + st * STAGE;
        const int ktok = b * SS + kt * BK;
        #pragma unroll
        for (int it = 0; it < 4; it++) {
            int lin = t + it * 256;
            int kr = lin >> 4, kc = lin & 15;
            cpasync16(base + KH_S + sw256(kr, kc), g_Kh + (size_t)(ktok + kr) * DD + kc * 8);
            cpasync16(base + KL_S + sw256(kr, kc), g_Kl + (size_t)(ktok + kr) * DD + kc * 8);
            int vr = lin >> 3, vc = lin & 7;
            size_t vsrc = (size_t)(b * DD + vr) * SS + kt * BK + vc * 8;
            cpasync16(base + VH_S + sw128(vr, vc), g_Vth + vsrc);
            cpasync16(base + VL_S + sw128(vr, vc), g_Vtl + vsrc);
        }
        if (t < 16) cpasync16(sb + MK_OFF + st * 256 + t * 16, g_rk + ktok + t * 4);
        CP_COMMIT();
    };

    float o[16][4];
    #pragma unroll
    for (int i = 0; i < 16; i++) { o[i][0] = o[i][1] = o[i][2] = o[i][3] = 0.f; }
    float mr0 = -INFINITY, mr1 = -INFINITY, lr0 = 0.f, lr1 = 0.f;

    issue_stage(0);
    __syncthreads();

    for (int kt = 0; kt < NT; kt++) {
        const int st = kt & 1;
        const uint32_t base = sb + ST_OFF + st * STAGE;
        const float* smk = (const float*)(smem + MK_OFF + st * 256);
        if (kt + 1 < NT) { issue_stage(kt + 1); CP_WAIT1(); }
        else             { CP_WAIT0(); }
        __syncthreads();

        float S[8][4];
        #pragma unroll
        for (int i = 0; i < 8; i++) { S[i][0] = S[i][1] = S[i][2] = S[i][3] = 0.f; }
        #pragma unroll
        for (int kc = 0; kc < 8; kc++) {
            uint32_t Ah[4], Al[4];
            ldsm4(Ah, sb + QH_OFF + sw256(rowA, kc * 2 + hA));
            ldsm4(Al, sb + QL_OFF + sw256(rowA, kc * 2 + hA));
            #pragma unroll
            for (int np = 0; np < 4; np++) {
                uint32_t Bh[4], Bl[4];
                ldsm4(Bh, base + KH_S + sw256(np * 16 + rowB8, kc * 2 + hB));
                ldsm4(Bl, base + KL_S + sw256(np * 16 + rowB8, kc * 2 + hB));
                mma16816(S[2 * np], Ah, Bh);     mma16816(S[2 * np + 1], Ah, Bh + 2);
                mma16816(S[2 * np], Ah, Bl);     mma16816(S[2 * np + 1], Ah, Bl + 2);
                mma16816(S[2 * np], Al, Bh);     mma16816(S[2 * np + 1], Al, Bh + 2);
            }
        }

        const int cbase = 2 * (lane & 3);
        float tm0 = -INFINITY, tm1 = -INFINITY;
        #pragma unroll
        for (int nt = 0; nt < 8; nt++) {
            float2 mk2 = *reinterpret_cast<const float2*>(&smk[nt * 8 + cbase]);
            S[nt][0] += rq0 * mk2.x; S[nt][1] += rq0 * mk2.y;
            S[nt][2] += rq1 * mk2.x; S[nt][3] += rq1 * mk2.y;
            tm0 = fmaxf(tm0, fmaxf(S[nt][0], S[nt][1]));
            tm1 = fmaxf(tm1, fmaxf(S[nt][2], S[nt][3]));
        }
        tm0 = fmaxf(tm0, __shfl_xor_sync(0xFFFFFFFFu, tm0, 1));
        tm0 = fmaxf(tm0, __shfl_xor_sync(0xFFFFFFFFu, tm0, 2));
        tm1 = fmaxf(tm1, __shfl_xor_sync(0xFFFFFFFFu, tm1, 1));
        tm1 = fmaxf(tm1, __shfl_xor_sync(0xFFFFFFFFu, tm1, 2));
        float nm0 = fmaxf(mr0, tm0), nm1 = fmaxf(mr1, tm1);
        float al0 = __expf(mr0 - nm0), al1 = __expf(mr1 - nm1);
        mr0 = nm0; mr1 = nm1;

        uint32_t PhL[8], PhH[8], PlL[8], PlH[8];
        float s0 = 0.f, s1 = 0.f;
        #pragma unroll
        for (int nt = 0; nt < 8; nt++) {
            float p0 = __expf(S[nt][0] - nm0), p1 = __expf(S[nt][1] - nm0);
            float p2 = __expf(S[nt][2] - nm1), p3 = __expf(S[nt][3] - nm1);
            s0 += p0 + p1; s1 += p2 + p3;
            float h0 = __bfloat162float(__float2bfloat16(p0));
            float h1 = __bfloat162float(__float2bfloat16(p1));
            float h2 = __bfloat162float(__float2bfloat16(p2));
            float h3 = __bfloat162float(__float2bfloat16(p3));
            PhL[nt] = pack_bf16x2(h0, h1); PhH[nt] = pack_bf16x2(h2, h3);
            PlL[nt] = pack_bf16x2(p0 - h0, p1 - h1);
            PlH[nt] = pack_bf16x2(p2 - h2, p3 - h3);
        }
        s0 += __shfl_xor_sync(0xFFFFFFFFu, s0, 1);
        s0 += __shfl_xor_sync(0xFFFFFFFFu, s0, 2);
        s1 += __shfl_xor_sync(0xFFFFFFFFu, s1, 1);
        s1 += __shfl_xor_sync(0xFFFFFFFFu, s1, 2);
        lr0 = lr0 * al0 + s0; lr1 = lr1 * al1 + s1;
        #pragma unroll
        for (int i = 0; i < 16; i++) { o[i][0] *= al0; o[i][1] *= al0; o[i][2] *= al1; o[i][3] *= al1; }

        #pragma unroll
        for (int kc = 0; kc < 4; kc++) {
            uint32_t Aph[4] = {PhL[2 * kc], PhH[2 * kc], PhL[2 * kc + 1], PhH[2 * kc + 1]};
            uint32_t Apl[4] = {PlL[2 * kc], PlH[2 * kc], PlL[2 * kc + 1], PlH[2 * kc + 1]};
            #pragma unroll
            for (int dp = 0; dp < 8; dp++) {
                uint32_t Bh[4], Bl[4];
                ldsm4(Bh, base + VH_S + sw128(dp * 16 + rowB8, kc * 2 + hB));
                ldsm4(Bl, base + VL_S + sw128(dp * 16 + rowB8, kc * 2 + hB));
                mma16816(o[2 * dp], Aph, Bh);     mma16816(o[2 * dp + 1], Aph, Bh + 2);
                mma16816(o[2 * dp], Aph, Bl);     mma16816(o[2 * dp + 1], Aph, Bl + 2);
                mma16816(o[2 * dp], Apl, Bh);     mma16816(o[2 * dp + 1], Apl, Bh + 2);
            }
        }
        __syncthreads();
    }

    const float inv0 = 1.f / lr0, inv1 = 1.f / lr1;
    #pragma unroll
    for (int nt = 0; nt < 16; nt++) {
        int col = nt * 8 + 2 * (lane & 3);
        *reinterpret_cast<float2*>(outp + (size_t)r0g * DD + col) =
            make_float2(o[nt][0] * inv0, o[nt][1] * inv0);
        *reinterpret_cast<float2*>(outp + (size_t)(r0g + 8) * DD + col) =
            make_float2(o[nt][2] * inv1, o[nt][3] * inv1);
    }
}

extern "C" void kernel_launch(void* const* d_in, const int* in_sizes, int n_in,
                              void* d_out, int out_size) {
    const float* x  = (const float*)d_in[0];
    const float* wq = (const float*)d_in[2];
    const float* wk = (const float*)d_in[3];
    const float* wv = (const float*)d_in[4];
    float* out = (float*)d_out;

    cudaFuncSetAttribute(proj_kernel, cudaFuncAttributeMaxDynamicSharedMemorySize, PSMEM);
    cudaFuncSetAttribute(flash_mma_kernel, cudaFuncAttributeMaxDynamicSharedMemorySize, FSMEM_TOTAL);

    proj_kernel<<<dim3(128, 3), 256, PSMEM>>>(x, wq, wk, wv);
    flash_mma_kernel<<<BB * (SS / BQ), 256, FSMEM_TOTAL>>>(out);
}